// round 16
// baseline (speedup 1.0000x reference)
#include <cuda_runtime.h>
#include <cuda_bf16.h>
#include <math.h>
#include <stdint.h>

// ---------------- problem constants ----------------
#define BB   16
#define CH   128
#define HH   128
#define WW   128
#define HO   64
#define WO   64
#define TOK  4096
#define NT   65536
#define NG   128
#define QL   512
#define HB   8          // batches per half
#define HT   (HB*TOK)   // tokens per half
#define HG   (HB*8)     // groups per half

typedef unsigned long long ull;
typedef __nv_bfloat16 bf16;

// ---------------- fp32 scratch ----------------
__device__ __align__(256) float g_y  [(size_t)NT * 128];
__device__ __align__(256) float g_x1 [(size_t)NT * 128];
__device__ __align__(256) float g_t1 [(size_t)NT * 128];
__device__ __align__(256) float g_x3 [(size_t)NT * 128];
__device__ __align__(256) float g_gate[(size_t)NT * 128];
__device__ __align__(256) float g_dwt[(size_t)NT * 128];
__device__ __align__(256) float g_Sf [(size_t)NG * QL * QL];

// ---------------- split bf16 scratch ----------------
__device__ __align__(256) bf16 syL_h [(size_t)NT * 128];
__device__ __align__(256) bf16 syL_l [(size_t)NT * 128];
__device__ __align__(256) bf16 shlh_h[(size_t)NT * 256];
__device__ __align__(256) bf16 shlh_l[(size_t)NT * 256];
__device__ __align__(256) bf16 sy_h  [(size_t)NT * 128];
__device__ __align__(256) bf16 sy_l  [(size_t)NT * 128];
__device__ __align__(256) bf16 sS_h  [(size_t)NG * QL * QL];
__device__ __align__(256) bf16 sS_l  [(size_t)NG * QL * QL];
__device__ __align__(256) bf16 syT_h [(size_t)NG * 128 * 512];
__device__ __align__(256) bf16 syT_l [(size_t)NG * 128 * 512];
__device__ __align__(256) bf16 sattn_h[(size_t)NT * 128];
__device__ __align__(256) bf16 sattn_l[(size_t)NT * 128];
__device__ __align__(256) bf16 st0_h [(size_t)NT * 128];
__device__ __align__(256) bf16 st0_l [(size_t)NT * 128];
__device__ __align__(256) bf16 st0b_h[(size_t)NT * 128];
__device__ __align__(256) bf16 st0b_l[(size_t)NT * 128];
__device__ __align__(256) bf16 sx2_h [(size_t)NT * 128];
__device__ __align__(256) bf16 sx2_l [(size_t)NT * 128];
__device__ __align__(256) bf16 sx2b_h[(size_t)NT * 128];
__device__ __align__(256) bf16 sx2b_l[(size_t)NT * 128];
__device__ __align__(256) bf16 sW_h  [131072];
__device__ __align__(256) bf16 sW_l  [131072];
__device__ __align__(256) bf16 sWc_h [262144];
__device__ __align__(256) bf16 sWc_l [262144];
__device__ __align__(256) bf16 sxt_h [(size_t)BB * HH * WW * CH];
__device__ __align__(256) bf16 sxt_l [(size_t)BB * HH * WW * CH];

__device__ __forceinline__ float gelu_f(float v) {
    return 0.5f * v * (1.0f + erff(v * 0.70710678118654752f));
}
__device__ __forceinline__ uint32_t smem_u32(const void* p) {
    uint32_t a;
    asm("{ .reg .u64 t; cvta.to.shared.u64 t, %1; cvt.u32.u64 %0, t; }" : "=r"(a) : "l"(p));
    return a;
}
#define SW128(o) ((o) ^ (((o) >> 3) & 0x70))

__device__ __forceinline__ void st_split(bf16* H, bf16* L, size_t off, float v) {
    bf16 h = __float2bfloat16(v);
    H[off] = h;
    L[off] = __float2bfloat16(v - __bfloat162float(h));
}

__device__ __forceinline__ void ldm_x4(uint32_t* r, uint32_t addr) {
    asm volatile("ldmatrix.sync.aligned.m8n8.x4.shared.b16 {%0,%1,%2,%3}, [%4];"
                 : "=r"(r[0]), "=r"(r[1]), "=r"(r[2]), "=r"(r[3]) : "r"(addr));
}
__device__ __forceinline__ void mma_bf16(float* d, const uint32_t* a, const uint32_t* b) {
    asm volatile("mma.sync.aligned.m16n8k16.row.col.f32.bf16.bf16.f32 "
                 "{%0,%1,%2,%3}, {%4,%5,%6,%7}, {%8,%9}, {%0,%1,%2,%3};"
                 : "+f"(d[0]), "+f"(d[1]), "+f"(d[2]), "+f"(d[3])
                 : "r"(a[0]), "r"(a[1]), "r"(a[2]), "r"(a[3]), "r"(b[0]), "r"(b[1]));
}
__device__ __forceinline__ void cp16(uint32_t dst, const void* src) {
    asm volatile("cp.async.cg.shared.global [%0], [%1], 16;" :: "r"(dst), "l"(src));
}
__device__ __forceinline__ void cp16z(uint32_t dst, const void* src, int sz) {
    asm volatile("cp.async.cg.shared.global [%0], [%1], 16, %2;" :: "r"(dst), "l"(src), "r"(sz));
}

// ---------------- weight splits ----------------
__global__ void wsplit_k(const float* __restrict__ conv1_w, const float* __restrict__ fc1_w,
                         const float* __restrict__ div_w, const float* __restrict__ fc2_w,
                         const float* __restrict__ fc3a_w, const float* __restrict__ fc3b_w,
                         const float* __restrict__ act_w,
                         bf16* __restrict__ WH, bf16* __restrict__ WL) {
    int i = blockIdx.x * 256 + threadIdx.x;
    float v;
    if      (i <  32768) v = conv1_w[i];
    else if (i <  49152) v = fc1_w [i - 32768];
    else if (i <  65536) v = div_w [i - 49152];
    else if (i <  81920) v = fc2_w [i - 65536];
    else if (i <  98304) v = fc3a_w[i - 81920];
    else if (i < 114688) v = fc3b_w[i - 98304];
    else                 v = act_w [i - 114688];
    bf16 h = __float2bfloat16(v);
    WH[i] = h;
    WL[i] = __float2bfloat16(v - __bfloat162float(h));
}

__global__ void wconv_k(const float* __restrict__ l1_w,
                        bf16* __restrict__ WH, bf16* __restrict__ WL) {
    int i = blockIdx.x * 256 + threadIdx.x;
    int oc = i >> 11;
    int k = i & 2047;
    int tap = k >> 7, ic = k & 127;
    float v = l1_w[oc * 2048 + ic * 16 + tap];
    bf16 h = __float2bfloat16(v);
    WH[i] = h;
    WL[i] = __float2bfloat16(v - __bfloat162float(h));
}

// ---------------- x NCHW -> NHWC split (per half) ----------------
__global__ void nhwc_k(const float* __restrict__ x,
                       bf16* __restrict__ xh, bf16* __restrict__ xl, int b_off) {
    __shared__ float tile[32][129];
    int h = blockIdx.x, b = blockIdx.y + b_off, tid = threadIdx.x;
    for (int cc = 0; cc < 4; cc++) {
        for (int idx = tid; idx < 32 * 128; idx += 256) {
            int cl = idx >> 7, w = idx & 127;
            tile[cl][w] = x[(((size_t)b * CH + cc * 32 + cl) * HH + h) * WW + w];
        }
        __syncthreads();
        for (int idx = tid; idx < 128 * 32; idx += 256) {
            int w = idx >> 5, cl = idx & 31;
            size_t o = (((size_t)b * HH + h) * WW + w) * CH + cc * 32 + cl;
            st_split(xh, xl, o, tile[cl][w]);
        }
        __syncthreads();
    }
}

// ---------------- Haar DWT -> split token layouts (per half) ----------------
__global__ void haar_k(const float* __restrict__ x,
                       bf16* __restrict__ yLh, bf16* __restrict__ yLl,
                       bf16* __restrict__ yTh, bf16* __restrict__ yTl,
                       bf16* __restrict__ hlhh, bf16* __restrict__ hlhl, int b_off) {
    __shared__ float sLL[32][65], sHL[32][65], sLH[32][65], sHH[32][65];
    int i = blockIdx.x, b = blockIdx.y + b_off, tid = threadIdx.x;
    for (int cc = 0; cc < 4; cc++) {
        for (int idx = tid; idx < 32 * 64; idx += 256) {
            int cl = idx / 64, j = idx % 64;
            int c = cc * 32 + cl;
            const float* base = x + (((long long)(b * CH + c) * HH + 2 * i) * WW) + 2 * j;
            float a = base[0], bb2 = base[1], cv = base[WW], d = base[WW + 1];
            sLL[cl][j] = (a + bb2 + cv + d) * 0.5f;
            sHL[cl][j] = (a - bb2 + cv - d) * 0.5f;
            sLH[cl][j] = (a + bb2 - cv - d) * 0.5f;
            sHH[cl][j] = (a - bb2 - cv + d) * 0.5f;
        }
        __syncthreads();
        for (int idx = tid; idx < 64 * 32; idx += 256) {
            int j = idx / 32, cl = idx % 32;
            size_t t = (size_t)b * TOK + i * 64 + j;
            int c = cc * 32 + cl;
            st_split(yLh, yLl, t * 128 + c, sLL[cl][j]);
            st_split(hlhh, hlhl, t * 256 + c, sHL[cl][j]);
            st_split(hlhh, hlhl, t * 256 + 128 + c, sLH[cl][j]);
        }
        {
            int g = b * 8 + (i >> 3);
            int qoff = (i & 7) * 64;
            for (int idx = tid; idx < 32 * 64; idx += 256) {
                int cl = idx / 64, j = idx % 64;
                int c = cc * 32 + cl;
                st_split(yTh, yTl, ((size_t)g * 128 + c) * 512 + qoff + j, sHH[cl][j]);
            }
        }
        __syncthreads();
    }
}

// ---------------- split-bf16 cp.async 3-stage pipelined GEMM ----------------
#define BGE_SMEM 196608
#define STG 65536

__device__ __forceinline__ void issue_chunk(
    const bf16* __restrict__ Ahi, const bf16* __restrict__ Alo, int lda,
    const bf16* __restrict__ Bhi, const bf16* __restrict__ Blo, int ldb,
    int k0, uint32_t base, int t) {
#pragma unroll
    for (int q = 0; q < 4; q++) {
        int idx = q * 256 + t;
        int row = idx >> 3, gg = idx & 7;
        uint32_t sw = SW128((uint32_t)(row * 128 + gg * 16));
        cp16(base + sw,         Ahi + (long long)row * lda + k0 + gg * 8);
        cp16(base + 16384 + sw, Alo + (long long)row * lda + k0 + gg * 8);
        cp16(base + 32768 + sw, Bhi + (long long)row * ldb + k0 + gg * 8);
        cp16(base + 49152 + sw, Blo + (long long)row * ldb + k0 + gg * 8);
    }
}

template <int EPI, int OMODE>
__global__ __launch_bounds__(256)
void bgemm_k(const bf16* __restrict__ Ahi, const bf16* __restrict__ Alo, long long sAg, int lda,
             const bf16* __restrict__ Bhi, const bf16* __restrict__ Blo, long long sBg, int ldb,
             float* __restrict__ Cf, bf16* __restrict__ Chi, bf16* __restrict__ Clo,
             long long sCg, int ldc, int K, float alpha,
             const float* __restrict__ bias, const float* __restrict__ extra) {
    extern __shared__ char smem[];
    uint32_t sb = smem_u32(smem);
    int t = threadIdx.x;
    int wid = t >> 5, lane = t & 31;
    int n0 = blockIdx.x * 128;
    int m0 = blockIdx.y * 128;
    int g = blockIdx.z;
    Ahi += (long long)g * sAg + (long long)m0 * lda;
    Alo += (long long)g * sAg + (long long)m0 * lda;
    Bhi += (long long)g * sBg + (long long)n0 * ldb;
    Blo += (long long)g * sBg + (long long)n0 * ldb;
    long long co = (long long)g * sCg;

    int wm = wid >> 2;
    int wn = wid & 3;

    float acc[4][4][4];
#pragma unroll
    for (int mi = 0; mi < 4; mi++)
#pragma unroll
        for (int ni = 0; ni < 4; ni++)
#pragma unroll
            for (int e = 0; e < 4; e++) acc[mi][ni][e] = 0.f;

    int a_row_l = lane & 15;
    int a_k8    = (lane >> 4) << 3;
    int b_row2  = (lane & 7) + ((lane >> 4) << 3);
    int b_k8    = ((lane >> 3) & 1) << 3;

    int nchunks = K >> 6;
    issue_chunk(Ahi, Alo, lda, Bhi, Blo, ldb, 0, sb, t);
    asm volatile("cp.async.commit_group;" ::: "memory");
    if (nchunks > 1) {
        issue_chunk(Ahi, Alo, lda, Bhi, Blo, ldb, 64, sb + STG, t);
        asm volatile("cp.async.commit_group;" ::: "memory");
    }

    for (int ch = 0; ch < nchunks; ch++) {
        if (ch + 1 < nchunks) asm volatile("cp.async.wait_group 1;" ::: "memory");
        else                  asm volatile("cp.async.wait_group 0;" ::: "memory");
        __syncthreads();
        if (ch + 2 < nchunks) {
            issue_chunk(Ahi, Alo, lda, Bhi, Blo, ldb, (ch + 2) * 64,
                        sb + ((ch + 2) % 3) * STG, t);
            asm volatile("cp.async.commit_group;" ::: "memory");
        }
        uint32_t base = sb + (ch % 3) * STG;
        uint32_t aHiA = base, aLoA = base + 16384, bHiA = base + 32768, bLoA = base + 49152;
#pragma unroll
        for (int ks = 0; ks < 4; ks++) {
            uint32_t Bh[4][2], Bl[4][2];
#pragma unroll
            for (int np = 0; np < 2; np++) {
                uint32_t byte = (uint32_t)((wn * 32 + np * 16 + b_row2) * 128 +
                                           (ks * 16 + b_k8) * 2);
                uint32_t sw = SW128(byte);
                uint32_t r4[4];
                ldm_x4(r4, bHiA + sw);
                Bh[2 * np][0] = r4[0]; Bh[2 * np][1] = r4[1];
                Bh[2 * np + 1][0] = r4[2]; Bh[2 * np + 1][1] = r4[3];
                ldm_x4(r4, bLoA + sw);
                Bl[2 * np][0] = r4[0]; Bl[2 * np][1] = r4[1];
                Bl[2 * np + 1][0] = r4[2]; Bl[2 * np + 1][1] = r4[3];
            }
#pragma unroll
            for (int mi = 0; mi < 4; mi++) {
                uint32_t Ah[4], Al[4];
                uint32_t byte = (uint32_t)((wm * 64 + mi * 16 + a_row_l) * 128 +
                                           (ks * 16 + a_k8) * 2);
                uint32_t sw = SW128(byte);
                ldm_x4(Ah, aHiA + sw);
                ldm_x4(Al, aLoA + sw);
#pragma unroll
                for (int ni = 0; ni < 4; ni++) {
                    mma_bf16(acc[mi][ni], Ah, Bh[ni]);
                    mma_bf16(acc[mi][ni], Ah, Bl[ni]);
                    mma_bf16(acc[mi][ni], Al, Bh[ni]);
                }
            }
        }
        __syncthreads();
    }

    int rbase = m0 + wm * 64 + (lane >> 2);
    int cbase = n0 + wn * 32 + (lane & 3) * 2;
#pragma unroll
    for (int mi = 0; mi < 4; mi++) {
#pragma unroll
        for (int h = 0; h < 2; h++) {
            int m = rbase + mi * 16 + h * 8;
            long long rowoff = co + (long long)m * ldc;
#pragma unroll
            for (int ni = 0; ni < 4; ni++) {
                int c = cbase + ni * 8;
                float v0 = acc[mi][ni][2 * h]     * alpha;
                float v1 = acc[mi][ni][2 * h + 1] * alpha;
                if (bias) { v0 += bias[c]; v1 += bias[c + 1]; }
                if (EPI == 1 || EPI == 3) { v0 = gelu_f(v0); v1 = gelu_f(v1); }
                if (EPI == 2) {
                    v0 = 1.f / (1.f + expf(-v0));
                    v1 = 1.f / (1.f + expf(-v1));
                }
                if (EPI == 3) {
                    float2 ev = *reinterpret_cast<const float2*>(&extra[rowoff + c]);
                    v0 -= ev.x; v1 -= ev.y;
                }
                if (OMODE & 1) {
                    float2 o; o.x = v0; o.y = v1;
                    *reinterpret_cast<float2*>(&Cf[rowoff + c]) = o;
                }
                if (OMODE & 2) {
                    bf16 h0 = __float2bfloat16(v0), h1 = __float2bfloat16(v1);
                    __nv_bfloat162 hp, lp;
                    hp.x = h0; hp.y = h1;
                    lp.x = __float2bfloat16(v0 - __bfloat162float(h0));
                    lp.y = __float2bfloat16(v1 - __bfloat162float(h1));
                    *reinterpret_cast<__nv_bfloat162*>(&Chi[rowoff + c]) = hp;
                    *reinterpret_cast<__nv_bfloat162*>(&Clo[rowoff + c]) = lp;
                }
            }
        }
    }
}

// ---------------- conv 4x4 s2 p1 as implicit GEMM (per half) ----------------
__device__ __forceinline__ void issue_conv_chunk(
    const bf16* __restrict__ xh, const bf16* __restrict__ xl,
    const bf16* __restrict__ wh, const bf16* __restrict__ wl,
    int b, const int* iq, const int* jq, int ch, uint32_t base, int t) {
    int tap = ch >> 1;
    int icH = (ch & 1) * 64;
    int r = tap >> 2, s = tap & 3;
#pragma unroll
    for (int q = 0; q < 4; q++) {
        int idx = q * 256 + t;
        int row = idx >> 3, gg = idx & 7;
        uint32_t sw = SW128((uint32_t)(row * 128 + gg * 16));
        int yy = 2 * iq[q] - 1 + r;
        int xx = 2 * jq[q] - 1 + s;
        bool ok = ((unsigned)yy < 128u) && ((unsigned)xx < 128u);
        int yyc = ok ? yy : 0, xxc = ok ? xx : 0;
        size_t off = ((((size_t)b * HH + yyc) * WW + xxc) * CH) + icH + gg * 8;
        int sz = ok ? 16 : 0;
        cp16z(base + sw,         xh + off, sz);
        cp16z(base + 16384 + sw, xl + off, sz);
        size_t woff = (size_t)row * 2048 + ch * 64 + gg * 8;
        cp16(base + 32768 + sw, wh + woff);
        cp16(base + 49152 + sw, wl + woff);
    }
}

__global__ __launch_bounds__(256)
void cgemm_k(const bf16* __restrict__ xh, const bf16* __restrict__ xl,
             const bf16* __restrict__ wh, const bf16* __restrict__ wl,
             const float* __restrict__ bias, float* __restrict__ dwt, int b_off) {
    extern __shared__ char smem[];
    uint32_t sb = smem_u32(smem);
    int t = threadIdx.x;
    int wid = t >> 5, lane = t & 31;
    int my = blockIdx.y;
    int b = blockIdx.z + b_off;
    int wm = wid >> 2;
    int wn = wid & 3;

    int iq[4], jq[4];
#pragma unroll
    for (int q = 0; q < 4; q++) {
        int idx = q * 256 + t;
        int m = my * 128 + (idx >> 3);
        iq[q] = m >> 6;
        jq[q] = m & 63;
    }

    float acc[4][4][4];
#pragma unroll
    for (int mi = 0; mi < 4; mi++)
#pragma unroll
        for (int ni = 0; ni < 4; ni++)
#pragma unroll
            for (int e = 0; e < 4; e++) acc[mi][ni][e] = 0.f;

    int a_row_l = lane & 15;
    int a_k8    = (lane >> 4) << 3;
    int b_row2  = (lane & 7) + ((lane >> 4) << 3);
    int b_k8    = ((lane >> 3) & 1) << 3;

    issue_conv_chunk(xh, xl, wh, wl, b, iq, jq, 0, sb, t);
    asm volatile("cp.async.commit_group;" ::: "memory");
    issue_conv_chunk(xh, xl, wh, wl, b, iq, jq, 1, sb + STG, t);
    asm volatile("cp.async.commit_group;" ::: "memory");

    for (int ch = 0; ch < 32; ch++) {
        if (ch + 1 < 32) asm volatile("cp.async.wait_group 1;" ::: "memory");
        else             asm volatile("cp.async.wait_group 0;" ::: "memory");
        __syncthreads();
        if (ch + 2 < 32) {
            issue_conv_chunk(xh, xl, wh, wl, b, iq, jq, ch + 2,
                             sb + ((ch + 2) % 3) * STG, t);
            asm volatile("cp.async.commit_group;" ::: "memory");
        }
        uint32_t base = sb + (ch % 3) * STG;
        uint32_t aHiA = base, aLoA = base + 16384, bHiA = base + 32768, bLoA = base + 49152;
#pragma unroll
        for (int ks = 0; ks < 4; ks++) {
            uint32_t Bh[4][2], Bl[4][2];
#pragma unroll
            for (int np = 0; np < 2; np++) {
                uint32_t byte = (uint32_t)((wn * 32 + np * 16 + b_row2) * 128 +
                                           (ks * 16 + b_k8) * 2);
                uint32_t sw = SW128(byte);
                uint32_t r4[4];
                ldm_x4(r4, bHiA + sw);
                Bh[2 * np][0] = r4[0]; Bh[2 * np][1] = r4[1];
                Bh[2 * np + 1][0] = r4[2]; Bh[2 * np + 1][1] = r4[3];
                ldm_x4(r4, bLoA + sw);
                Bl[2 * np][0] = r4[0]; Bl[2 * np][1] = r4[1];
                Bl[2 * np + 1][0] = r4[2]; Bl[2 * np + 1][1] = r4[3];
            }
#pragma unroll
            for (int mi = 0; mi < 4; mi++) {
                uint32_t Ah[4], Al[4];
                uint32_t byte = (uint32_t)((wm * 64 + mi * 16 + a_row_l) * 128 +
                                           (ks * 16 + a_k8) * 2);
                uint32_t sw = SW128(byte);
                ldm_x4(Ah, aHiA + sw);
                ldm_x4(Al, aLoA + sw);
#pragma unroll
                for (int ni = 0; ni < 4; ni++) {
                    mma_bf16(acc[mi][ni], Ah, Bh[ni]);
                    mma_bf16(acc[mi][ni], Ah, Bl[ni]);
                    mma_bf16(acc[mi][ni], Al, Bh[ni]);
                }
            }
        }
        __syncthreads();
    }

    int rbase = my * 128 + wm * 64 + (lane >> 2);
    int cbase = wn * 32 + (lane & 3) * 2;
#pragma unroll
    for (int mi = 0; mi < 4; mi++) {
#pragma unroll
        for (int h = 0; h < 2; h++) {
            int m = rbase + mi * 16 + h * 8;
            size_t rowoff = ((size_t)b * TOK + m) * 128;
#pragma unroll
            for (int ni = 0; ni < 4; ni++) {
                int c = cbase + ni * 8;
                float v0 = acc[mi][ni][2 * h]     + bias[c];
                float v1 = acc[mi][ni][2 * h + 1] + bias[c + 1];
                float2 o;
                o.x = fmaxf(v0, 0.f);
                o.y = fmaxf(v1, 0.f);
                *reinterpret_cast<float2*>(&dwt[rowoff + c]) = o;
            }
        }
    }
}

// ---------------- smem-resident column softmax over q ----------------
#define SMX_SMEM 65536
__global__ __launch_bounds__(256)
void softmax2_k(const float* __restrict__ Sf, bf16* __restrict__ Sh, bf16* __restrict__ Sl) {
    extern __shared__ float tile[];
    __shared__ float red[8][32];
    int g = blockIdx.y;
    int k0 = blockIdx.x * 32;
    int t = threadIdx.x;
    int kc = t & 31, qh = t >> 5;
    const float* Sg = Sf + (size_t)g * QL * QL + k0 + kc;
    for (int q = qh; q < QL; q += 8)
        tile[q * 32 + kc] = Sg[(size_t)q * QL];
    __syncthreads();
    float m = -INFINITY;
    for (int q = qh; q < QL; q += 8) m = fmaxf(m, tile[q * 32 + kc]);
    red[qh][kc] = m;
    __syncthreads();
    if (t < 32) {
        float M = red[0][kc];
#pragma unroll
        for (int r = 1; r < 8; r++) M = fmaxf(M, red[r][kc]);
        red[0][kc] = M;
    }
    __syncthreads();
    float M = red[0][kc];
    __syncthreads();
    float s = 0.f;
    for (int q = qh; q < QL; q += 8) {
        float e = expf(tile[q * 32 + kc] - M);
        tile[q * 32 + kc] = e;
        s += e;
    }
    red[qh][kc] = s;
    __syncthreads();
    if (t < 32) {
        float S = 0.f;
#pragma unroll
        for (int r = 0; r < 8; r++) S += red[r][kc];
        red[0][kc] = 1.f / S;
    }
    __syncthreads();
    float inv = red[0][kc];
    size_t obase = (size_t)g * QL * QL + k0 + kc;
    for (int q = qh; q < QL; q += 8) {
        float p = tile[q * 32 + kc] * inv;
        bf16 h = __float2bfloat16(p);
        Sh[obase + (size_t)q * QL] = h;
        Sl[obase + (size_t)q * QL] = __float2bfloat16(p - __bfloat162float(h));
    }
}

// ---------------- per-token layernorm (split in/out) ----------------
__global__ void ln_k(const bf16* __restrict__ Xh, const bf16* __restrict__ Xl,
                     bf16* __restrict__ Yh, bf16* __restrict__ Yl,
                     const float* __restrict__ gw, const float* __restrict__ bw) {
    int warp = threadIdx.x / 32, lane = threadIdx.x % 32;
    size_t t = (size_t)blockIdx.x * 8 + warp;
    float v[4];
    float sum = 0.f;
#pragma unroll
    for (int i = 0; i < 4; i++) {
        size_t off = t * 128 + lane + 32 * i;
        v[i] = __bfloat162float(Xh[off]) + __bfloat162float(Xl[off]);
        sum += v[i];
    }
#pragma unroll
    for (int o = 16; o; o >>= 1) sum += __shfl_xor_sync(0xffffffffu, sum, o);
    float mean = sum * (1.f / 128.f);
    float vs = 0.f;
#pragma unroll
    for (int i = 0; i < 4; i++) { float d = v[i] - mean; vs += d * d; }
#pragma unroll
    for (int o = 16; o; o >>= 1) vs += __shfl_xor_sync(0xffffffffu, vs, o);
    float inv = rsqrtf(vs * (1.f / 128.f) + 1e-5f);
#pragma unroll
    for (int i = 0; i < 4; i++) {
        int c = lane + 32 * i;
        float r = (v[i] - mean) * inv * gw[c] + bw[c];
        st_split(Yh, Yl, t * 128 + c, r);
    }
}

// ---------------- fused: ffn=gate*LN(t1+x3) + final combine (per half) ----------------
#define FIN_SMEM (64 * 129 * 4)
__global__ __launch_bounds__(256)
void final2_k(const float* __restrict__ x,
              const float* __restrict__ T1, const float* __restrict__ X3,
              const float* __restrict__ G,
              const float* __restrict__ gw, const float* __restrict__ bw,
              const float* __restrict__ ytok, const float* __restrict__ dwt,
              float* __restrict__ out, int b_off) {
    extern __shared__ float sff[];
    __shared__ float sy[32][65], sd[32][65];
    int i = blockIdx.x, b = blockIdx.y + b_off, tid = threadIdx.x;
    int warp = tid >> 5, lane = tid & 31;

#pragma unroll
    for (int tt = 0; tt < 8; tt++) {
        int tl = warp * 8 + tt;
        size_t tg = ((size_t)b * TOK + i * 64 + tl) * 128;
        float v[4];
        float sum = 0.f;
#pragma unroll
        for (int e = 0; e < 4; e++) {
            size_t c = tg + lane + 32 * e;
            v[e] = T1[c] + X3[c];
            sum += v[e];
        }
#pragma unroll
        for (int o = 16; o; o >>= 1) sum += __shfl_xor_sync(0xffffffffu, sum, o);
        float mean = sum * (1.f / 128.f);
        float vs = 0.f;
#pragma unroll
        for (int e = 0; e < 4; e++) { float d = v[e] - mean; vs += d * d; }
#pragma unroll
        for (int o = 16; o; o >>= 1) vs += __shfl_xor_sync(0xffffffffu, vs, o);
        float inv = rsqrtf(vs * (1.f / 128.f) + 1e-5f);
#pragma unroll
        for (int e = 0; e < 4; e++) {
            int c = lane + 32 * e;
            float nrm = (v[e] - mean) * inv * gw[c] + bw[c];
            sff[tl * 129 + c] = G[tg + c] * nrm;
        }
    }
    __syncthreads();

    float pos_i = (float)(i * 127) / 63.f;
    int y0 = (int)floorf(pos_i);
    int y1 = min(y0 + 1, 127);
    float wy = pos_i - (float)y0;
    for (int cc = 0; cc < 4; cc++) {
        for (int idx = tid; idx < 64 * 32; idx += 256) {
            int j = idx / 32, cl = idx % 32;
            size_t t = (size_t)b * TOK + i * 64 + j;
            sy[cl][j] = ytok[t * 128 + cc * 32 + cl];
            sd[cl][j] = dwt[t * 128 + cc * 32 + cl];
        }
        __syncthreads();
        for (int idx = tid; idx < 32 * 64; idx += 256) {
            int cl = idx / 64, j = idx % 64;
            int c = cc * 32 + cl;
            float pos_j = (float)(j * 127) / 63.f;
            int x0 = (int)floorf(pos_j);
            int x1i = min(x0 + 1, 127);
            float wx = pos_j - (float)x0;
            const float* xb = x + (long long)(b * CH + c) * HH * WW;
            float r0 = xb[y0 * WW + x0] * (1.f - wy) + xb[y1 * WW + x0] * wy;
            float r1 = xb[y0 * WW + x1i] * (1.f - wy) + xb[y1 * WW + x1i] * wy;
            float dv = r0 * (1.f - wx) + r1 * wx;
            long long oi = (((long long)b * CH + c) * HO + i) * WO + j;
            out[oi] = sff[j * 129 + c] * (dv - sd[cl][j]) + sy[cl][j];
        }
        __syncthreads();
    }
}

// ---------------- launch: two batch halves, 3-stream budget ----------------
extern "C" void kernel_launch(void* const* d_in, const int* in_sizes, int n_in,
                              void* d_out, int out_size) {
    (void)in_sizes; (void)n_in; (void)out_size;
    const float* x       = (const float*)d_in[0];
    const float* conv1_b = (const float*)d_in[2];
    const float* l1_w    = (const float*)d_in[3];
    const float* l1_b    = (const float*)d_in[4];
    const float* ln1_g   = (const float*)d_in[5];
    const float* ln1_b   = (const float*)d_in[6];
    const float* fc1_b   = (const float*)d_in[8];
    const float* div_b   = (const float*)d_in[10];
    const float* fc2_b   = (const float*)d_in[12];
    const float* ln3_g   = (const float*)d_in[13];
    const float* ln3_b   = (const float*)d_in[14];
    const float* fc3a_b  = (const float*)d_in[16];
    const float* fc3b_b  = (const float*)d_in[18];
    const float* lnn_g   = (const float*)d_in[19];
    const float* lnn_b   = (const float*)d_in[20];
    const float* act_b   = (const float*)d_in[22];
    float* out = (float*)d_out;

    float *y, *x1, *t1, *x3, *gate, *dwt, *Sf;
    cudaGetSymbolAddress((void**)&y,    g_y);
    cudaGetSymbolAddress((void**)&x1,   g_x1);
    cudaGetSymbolAddress((void**)&t1,   g_t1);
    cudaGetSymbolAddress((void**)&x3,   g_x3);
    cudaGetSymbolAddress((void**)&gate, g_gate);
    cudaGetSymbolAddress((void**)&dwt,  g_dwt);
    cudaGetSymbolAddress((void**)&Sf,   g_Sf);

    bf16 *yLh, *yLl, *hlhh, *hlhl, *yh, *yl, *Sh, *Sl, *yTh, *yTl;
    bf16 *attnh, *attnl, *t0h, *t0l, *t0bh, *t0bl, *x2h, *x2l, *x2bh, *x2bl;
    bf16 *Wh, *Wl, *Wch, *Wcl, *xth, *xtl;
    cudaGetSymbolAddress((void**)&yLh,   syL_h);
    cudaGetSymbolAddress((void**)&yLl,   syL_l);
    cudaGetSymbolAddress((void**)&hlhh,  shlh_h);
    cudaGetSymbolAddress((void**)&hlhl,  shlh_l);
    cudaGetSymbolAddress((void**)&yh,    sy_h);
    cudaGetSymbolAddress((void**)&yl,    sy_l);
    cudaGetSymbolAddress((void**)&Sh,    sS_h);
    cudaGetSymbolAddress((void**)&Sl,    sS_l);
    cudaGetSymbolAddress((void**)&yTh,   syT_h);
    cudaGetSymbolAddress((void**)&yTl,   syT_l);
    cudaGetSymbolAddress((void**)&attnh, sattn_h);
    cudaGetSymbolAddress((void**)&attnl, sattn_l);
    cudaGetSymbolAddress((void**)&t0h,   st0_h);
    cudaGetSymbolAddress((void**)&t0l,   st0_l);
    cudaGetSymbolAddress((void**)&t0bh,  st0b_h);
    cudaGetSymbolAddress((void**)&t0bl,  st0b_l);
    cudaGetSymbolAddress((void**)&x2h,   sx2_h);
    cudaGetSymbolAddress((void**)&x2l,   sx2_l);
    cudaGetSymbolAddress((void**)&x2bh,  sx2b_h);
    cudaGetSymbolAddress((void**)&x2bl,  sx2b_l);
    cudaGetSymbolAddress((void**)&Wh,    sW_h);
    cudaGetSymbolAddress((void**)&Wl,    sW_l);
    cudaGetSymbolAddress((void**)&Wch,   sWc_h);
    cudaGetSymbolAddress((void**)&Wcl,   sWc_l);
    cudaGetSymbolAddress((void**)&xth,   sxt_h);
    cudaGetSymbolAddress((void**)&xtl,   sxt_l);

    cudaFuncSetAttribute(bgemm_k<0,3>, cudaFuncAttributeMaxDynamicSharedMemorySize, BGE_SMEM);
    cudaFuncSetAttribute(bgemm_k<0,1>, cudaFuncAttributeMaxDynamicSharedMemorySize, BGE_SMEM);
    cudaFuncSetAttribute(bgemm_k<0,2>, cudaFuncAttributeMaxDynamicSharedMemorySize, BGE_SMEM);
    cudaFuncSetAttribute(bgemm_k<1,1>, cudaFuncAttributeMaxDynamicSharedMemorySize, BGE_SMEM);
    cudaFuncSetAttribute(bgemm_k<1,2>, cudaFuncAttributeMaxDynamicSharedMemorySize, BGE_SMEM);
    cudaFuncSetAttribute(bgemm_k<3,2>, cudaFuncAttributeMaxDynamicSharedMemorySize, BGE_SMEM);
    cudaFuncSetAttribute(bgemm_k<2,1>, cudaFuncAttributeMaxDynamicSharedMemorySize, BGE_SMEM);
    cudaFuncSetAttribute(cgemm_k, cudaFuncAttributeMaxDynamicSharedMemorySize, BGE_SMEM);
    cudaFuncSetAttribute(softmax2_k, cudaFuncAttributeMaxDynamicSharedMemorySize, SMX_SMEM);
    cudaFuncSetAttribute(final2_k, cudaFuncAttributeMaxDynamicSharedMemorySize, FIN_SMEM);

    // exactly 3 created streams (same budget as passing builds)
    static cudaStream_t sH1 = nullptr, sA = nullptr, sB2 = nullptr;
    static cudaEvent_t e0, eW, eAttn[2], eB[2], eC[2], eConv[2], eF1;
    if (!sH1) {
        cudaStreamCreateWithFlags(&sH1, cudaStreamNonBlocking);
        cudaStreamCreateWithFlags(&sA, cudaStreamNonBlocking);
        cudaStreamCreateWithFlags(&sB2, cudaStreamNonBlocking);
        cudaEventCreateWithFlags(&e0, cudaEventDisableTiming);
        cudaEventCreateWithFlags(&eW, cudaEventDisableTiming);
        cudaEventCreateWithFlags(&eF1, cudaEventDisableTiming);
        for (int h = 0; h < 2; h++) {
            cudaEventCreateWithFlags(&eAttn[h], cudaEventDisableTiming);
            cudaEventCreateWithFlags(&eB[h], cudaEventDisableTiming);
            cudaEventCreateWithFlags(&eC[h], cudaEventDisableTiming);
            cudaEventCreateWithFlags(&eConv[h], cudaEventDisableTiming);
        }
    }

    const float* w0 = (const float*)d_in[1];
    const float* w1 = (const float*)d_in[7];
    const float* w2 = (const float*)d_in[9];
    const float* w3 = (const float*)d_in[11];
    const float* w4 = (const float*)d_in[15];
    const float* w5 = (const float*)d_in[17];
    const float* w6 = (const float*)d_in[21];

    cudaEventRecord(e0, 0);
    cudaStreamWaitEvent(sH1, e0, 0);
    cudaStreamWaitEvent(sA, e0, 0);
    cudaStreamWaitEvent(sB2, e0, 0);

    // weights on default; half-1 chain waits on them
    wsplit_k<<<512, 256>>>(w0, w1, w2, w3, w4, w5, w6, Wh, Wl);
    cudaEventRecord(eW, 0);
    cudaStreamWaitEvent(sH1, eW, 0);

    // conv branch (both halves, sequential on sA)
    wconv_k<<<1024, 256, 0, sA>>>(l1_w, Wch, Wcl);
    nhwc_k<<<dim3(128, HB), 256, 0, sA>>>(x, xth, xtl, 0);
    cgemm_k<<<dim3(1, 32, HB), 256, BGE_SMEM, sA>>>(xth, xtl, Wch, Wcl, l1_b, dwt, 0);
    cudaEventRecord(eConv[0], sA);
    nhwc_k<<<dim3(128, HB), 256, 0, sA>>>(x, xth, xtl, HB);
    cgemm_k<<<dim3(1, 32, HB), 256, BGE_SMEM, sA>>>(xth, xtl, Wch, Wcl, l1_b, dwt, HB);
    cudaEventRecord(eConv[1], sA);

    for (int h = 0; h < 2; h++) {
        cudaStream_t m = (h == 0) ? (cudaStream_t)0 : sH1;
        size_t TO = (size_t)h * HT * 128;
        size_t TO2 = (size_t)h * HT * 256;
        size_t GO = (size_t)h * HG * QL * QL;
        size_t VO = (size_t)h * HG * 128 * 512;
        int b0 = h * HB;

        // attention chain
        haar_k<<<dim3(64, HB), 256, 0, m>>>(x, yLh, yLl, yTh, yTl, hlhh, hlhl, b0);

        bgemm_k<0,3><<<dim3(1, HT / 128, 1), 256, BGE_SMEM, m>>>(
            hlhh + TO2, hlhl + TO2, 0, 256, Wh, Wl, 0, 256,
            y + TO, yh + TO, yl + TO, 0, 128, 256, 1.f, conv1_b, nullptr);

        bgemm_k<0,1><<<dim3(4, 4, HG), 256, BGE_SMEM, m>>>(
            yLh + TO, yLl + TO, (long long)QL * 128, 128,
            yh + TO, yl + TO, (long long)QL * 128, 128,
            Sf + GO, nullptr, nullptr, (long long)QL * QL, QL,
            128, 0.35355339059327373f, nullptr, nullptr);

        softmax2_k<<<dim3(16, HG), 256, SMX_SMEM, m>>>(Sf + GO, Sh + GO, Sl + GO);

        bgemm_k<0,2><<<dim3(1, 4, HG), 256, BGE_SMEM, m>>>(
            Sh + GO, Sl + GO, (long long)QL * QL, QL,
            yTh + VO, yTl + VO, (long long)128 * 512, 512,
            nullptr, attnh + TO, attnl + TO, (long long)QL * 128, 128, 512, 1.f, nullptr, nullptr);
        cudaEventRecord(eAttn[h], m);

        // side chain B on sB2: ln3 -> fc3a -> fc3b
        cudaStreamWaitEvent(sB2, eAttn[h], 0);
        ln_k<<<HT / 8, 256, 0, sB2>>>(attnh + TO, attnl + TO, t0bh + TO, t0bl + TO, ln3_g, ln3_b);
        bgemm_k<1,2><<<dim3(1, HT / 128), 256, BGE_SMEM, sB2>>>(
            t0bh + TO, t0bl + TO, 0, 128, Wh + 81920, Wl + 81920, 0, 128,
            nullptr, x2bh + TO, x2bl + TO, 0, 128, 128, 1.f, fc3a_b, nullptr);
        bgemm_k<0,1><<<dim3(1, HT / 128), 256, BGE_SMEM, sB2>>>(
            x2bh + TO, x2bl + TO, 0, 128, Wh + 98304, Wl + 98304, 0, 128,
            x3 + TO, nullptr, nullptr, 0, 128, 128, 1.f, fc3b_b, nullptr);
        cudaEventRecord(eB[h], sB2);

        // side chain C (gate) on sA, after its conv work
        cudaStreamWaitEvent(sA, eAttn[h], 0);
        bgemm_k<2,1><<<dim3(1, HT / 128), 256, BGE_SMEM, sA>>>(
            attnh + TO, attnl + TO, 0, 128, Wh + 114688, Wl + 114688, 0, 128,
            gate + TO, nullptr, nullptr, 0, 128, 128, 1.f, act_b, nullptr);
        cudaEventRecord(eC[h], sA);

        // main FFN chain
        ln_k<<<HT / 8, 256, 0, m>>>(attnh + TO, attnl + TO, t0h + TO, t0l + TO, ln1_g, ln1_b);
        bgemm_k<1,1><<<dim3(1, HT / 128), 256, BGE_SMEM, m>>>(
            t0h + TO, t0l + TO, 0, 128, Wh + 32768, Wl + 32768, 0, 128,
            x1 + TO, nullptr, nullptr, 0, 128, 128, 1.f, fc1_b, nullptr);
        bgemm_k<3,2><<<dim3(1, HT / 128), 256, BGE_SMEM, m>>>(
            attnh + TO, attnl + TO, 0, 128, Wh + 49152, Wl + 49152, 0, 128,
            nullptr, x2h + TO, x2l + TO, 0, 128, 128, 1.f, div_b, x1 + TO);
        bgemm_k<1,1><<<dim3(1, HT / 128), 256, BGE_SMEM, m>>>(
            x2h + TO, x2l + TO, 0, 128, Wh + 65536, Wl + 65536, 0, 128,
            t1 + TO, nullptr, nullptr, 0, 128, 128, 1.f, fc2_b, nullptr);

        // join this half
        cudaStreamWaitEvent(m, eB[h], 0);
        cudaStreamWaitEvent(m, eC[h], 0);
        cudaStreamWaitEvent(m, eConv[h], 0);
        final2_k<<<dim3(64, HB), 256, FIN_SMEM, m>>>(
            x, t1, x3, gate, lnn_g, lnn_b, y, dwt, out, b0);
    }

    // rejoin half-1 into origin stream
    cudaEventRecord(eF1, sH1);
    cudaStreamWaitEvent(0, eF1, 0);
}